// round 9
// baseline (speedup 1.0000x reference)
#include <cuda_runtime.h>

#define TSTEPS   512
#define NTHREADS 1024

// Padded strides (floats)
#define WSTRIDE  68     // weight row [Wih|Whh] = 64 + 4 pad
#define ISTRIDE  68     // input row per batch: 64 k + 4 pad
#define GSSTR    140    // gs row per batch: 128 gates + 12 pad (conflict-free ld & st)

// Dynamic smem layout (float offsets, 16B aligned)
#define OFF_W0    0                          // 128*68
#define OFF_W1    (OFF_W0 + 128*WSTRIDE)     // 8704
#define OFF_GS0   (OFF_W1 + 128*WSTRIDE)     // 17408: 32*140 activated gates L0 [b][g]
#define OFF_GS1   (OFF_GS0 + 32*GSSTR)       // 21888: L1
#define OFF_IN0   (OFF_GS1 + 32*GSSTR)       // 26368: 32*68 layer0 input [x | h0], [b][k]
#define OFF_INB   (OFF_IN0 + 32*ISTRIDE)     // 28544: layer1 input [h0 | h1]
#define OFF_B0    (OFF_INB + 32*ISTRIDE)     // 30720: 128
#define OFF_B1    (OFF_B0 + 128)             // 30848: 128
#define OFF_W1S   (OFF_B1 + 128)             // 30976: 32
#define OFF_B1S   (OFF_W1S + 32)             // 31008: 32
#define OFF_W2S   (OFF_B1S + 32)             // 31040: 64
#define SMEM_FLOATS (OFF_W2S + 64)           // 31104
#define SMEM_BYTES  (SMEM_FLOATS * 4)        // 124416

typedef unsigned long long ull;

__device__ __forceinline__ void upk2(ull v, float& lo, float& hi) {
    asm("mov.b64 {%0,%1}, %2;" : "=f"(lo), "=f"(hi) : "l"(v));
}
__device__ __forceinline__ void ffma2(ull& d, ull a, ull b) {
    asm("fma.rn.f32x2 %0, %1, %2, %0;" : "+l"(d) : "l"(a), "l"(b));
}
__device__ __forceinline__ float sigm(float v) {
    float e = __expf(-v);
    return __fdividef(1.0f, 1.0f + e);
}
__device__ __forceinline__ float tanh_(float v) {
    float e = __expf(-2.0f * v);
    return __fdividef(2.0f, 1.0f + e) - 1.0f;
}

// Gate phase for one layer: thread computes rows {gbase, gbase+64} x batches
// {2bp, 2bp+1}, applies the (statically known) activation, stores into
// gsL[b][row] (stride GSSTR=140 -> conflict-free stores & update loads).
// Row gbase in 0..63 => i/f gate => sigmoid. Row gbase+64 => g (tanh) if
// gbase<32 else o (sigmoid).
__device__ __forceinline__ void gate_phase_act(const float* __restrict__ Ws,
                                               const float* __restrict__ inX,
                                               float* __restrict__ gsL,
                                               int gbase, int bp,
                                               float bzA, float bzB, bool tanhB) {
    ull aE0 = 0, aO0 = 0, aE1 = 0, aO1 = 0;   // row gbase,    batch 0/1
    ull bE0 = 0, bO0 = 0, bE1 = 0, bO1 = 0;   // row gbase+64, batch 0/1
    const float* wA  = Ws + gbase * WSTRIDE;
    const float* wB  = Ws + (gbase + 64) * WSTRIDE;
    const float* ib0 = inX + (2 * bp) * ISTRIDE;
    const float* ib1 = ib0 + ISTRIDE;
#pragma unroll
    for (int kq = 0; kq < 16; kq++) {
        ulonglong2 i0 = *(const ulonglong2*)(ib0 + 4 * kq);
        ulonglong2 i1 = *(const ulonglong2*)(ib1 + 4 * kq);
        ulonglong2 wa = *(const ulonglong2*)(wA + 4 * kq);
        ulonglong2 wb = *(const ulonglong2*)(wB + 4 * kq);
        ffma2(aE0, wa.x, i0.x);  ffma2(aO0, wa.y, i0.y);
        ffma2(aE1, wa.x, i1.x);  ffma2(aO1, wa.y, i1.y);
        ffma2(bE0, wb.x, i0.x);  ffma2(bO0, wb.y, i0.y);
        ffma2(bE1, wb.x, i1.x);  ffma2(bO1, wb.y, i1.y);
    }
    float l0, h0, l1, h1;
    upk2(aE0, l0, h0); upk2(aO0, l1, h1);
    float gA0 = (l0 + h0) + (l1 + h1) + bzA;
    upk2(aE1, l0, h0); upk2(aO1, l1, h1);
    float gA1 = (l0 + h0) + (l1 + h1) + bzA;
    upk2(bE0, l0, h0); upk2(bO0, l1, h1);
    float gB0 = (l0 + h0) + (l1 + h1) + bzB;
    upk2(bE1, l0, h0); upk2(bO1, l1, h1);
    float gB1 = (l0 + h0) + (l1 + h1) + bzB;

    float aA0 = sigm(gA0);
    float aA1 = sigm(gA1);
    float aB0 = tanhB ? tanh_(gB0) : sigm(gB0);
    float aB1 = tanhB ? tanh_(gB1) : sigm(gB1);

    gsL[(2 * bp)     * GSSTR + gbase]      = aA0;
    gsL[(2 * bp + 1) * GSSTR + gbase]      = aA1;
    gsL[(2 * bp)     * GSSTR + 64 + gbase] = aB0;
    gsL[(2 * bp + 1) * GSSTR + 64 + gbase] = aB1;
}

// Update from pre-activated gates: thread (uj, ub) owns unit uj at batch ub.
__device__ __forceinline__ float upd(const float* __restrict__ gsL,
                                     int uj, int ub, float& c) {
    const float* g = gsL + ub * GSSTR;
    float iv = g[uj];
    float fv = g[32 + uj];
    float gv = g[64 + uj];
    float ov = g[96 + uj];
    c = fmaf(fv, c, iv * gv);
    return ov * tanh_(c);
}

__global__ void __launch_bounds__(NTHREADS, 1)
lstm_fused_kernel(const float* __restrict__ tensor,
                  const float* __restrict__ w1,   const float* __restrict__ b1,
                  const float* __restrict__ Wih0, const float* __restrict__ Whh0,
                  const float* __restrict__ bih0, const float* __restrict__ bhh0,
                  const float* __restrict__ Wih1, const float* __restrict__ Whh1,
                  const float* __restrict__ bih1, const float* __restrict__ bhh1,
                  const float* __restrict__ w2,   const float* __restrict__ b2,
                  float* __restrict__ out) {
    extern __shared__ float smem[];
    float* W0s   = smem + OFF_W0;
    float* W1s   = smem + OFF_W1;
    float* gs0   = smem + OFF_GS0;
    float* gs1   = smem + OFF_GS1;
    float* in0   = smem + OFF_IN0;
    float* inB   = smem + OFF_INB;
    float* bias0 = smem + OFF_B0;
    float* bias1 = smem + OFF_B1;
    float* w1s   = smem + OFF_W1S;
    float* b1s   = smem + OFF_B1S;
    float* w2s   = smem + OFF_W2S;

    const int tid = threadIdx.x;
    const int l   = tid & 31;
    const int wrp = tid >> 5;
    // Gate-phase mapping (8 distinct gate rows + 4 distinct batch pairs per warp)
    const int lg = l & 7;
    const int lb = l >> 3;
    const int gw = wrp & 7;
    const int bw = wrp >> 3;
    const int gbase = gw * 8 + lg;    // 0..63 -> rows gbase, gbase+64
    const int bp    = bw * 4 + lb;    // 0..15 -> batches 2bp, 2bp+1
    const bool tanhB = (gbase < 32);  // row gbase+64 is a 'g' gate (tanh)
    // Update-phase mapping
    const int uj = tid & 31;          // hidden unit
    const int ub = tid >> 5;          // batch

    // ---- Preload weights / biases into SMEM ----
    for (int idx = tid; idx < 128 * 32; idx += NTHREADS) {
        int g = idx >> 5, k = idx & 31;
        W0s[g * WSTRIDE + k]      = Wih0[idx];
        W0s[g * WSTRIDE + 32 + k] = Whh0[idx];
        W1s[g * WSTRIDE + k]      = Wih1[idx];
        W1s[g * WSTRIDE + 32 + k] = Whh1[idx];
    }
    if (tid < 128) {
        bias0[tid] = bih0[tid] + bhh0[tid];
        bias1[tid] = bih1[tid] + bhh1[tid];
    }
    if (tid < 32) { w1s[tid] = w1[tid]; b1s[tid] = b1[tid]; }
    if (tid < 64) { w2s[tid] = w2[tid]; }
    __syncthreads();

    // hoisted per-thread constants
    const float bz00 = bias0[gbase], bz01 = bias0[gbase + 64];
    const float bz10 = bias1[gbase], bz11 = bias1[gbase + 64];
    const float w1j  = w1s[uj], b1j = b1s[uj];
    const float* __restrict__ seq = tensor + (long)(blockIdx.x * 32 + ub) * TSTEPS;

    // ---- Init staging: x(t=0); h0 = h1 = 0 ----
    {
        float x0 = fmaxf(fmaf(seq[0], w1j, b1j), 0.f);
        in0[ub * ISTRIDE + uj]      = x0;
        in0[ub * ISTRIDE + 32 + uj] = 0.f;
        inB[ub * ISTRIDE + uj]      = 0.f;
        inB[ub * ISTRIDE + 32 + uj] = 0.f;
    }
    float c0 = 0.f, c1 = 0.f;
    __syncthreads();

    // Pipelined loop: iteration n computes L0 step n and L1 step n-1.
    // TSTEPS+1 iterations; edges predicated (uniform branches).
    for (int n = 0; n <= TSTEPS; n++) {
        // ---- Fused gate phase (both layers, activations applied here) ----
        if (n < TSTEPS) gate_phase_act(W0s, in0, gs0, gbase, bp, bz00, bz01, tanhB);
        if (n > 0)      gate_phase_act(W1s, inB, gs1, gbase, bp, bz10, bz11, tanhB);
        __syncthreads();                                   // S1: gates ready

        // ---- Fused update phase ----
        if (n < TSTEPS) {
            float h0 = upd(gs0, uj, ub, c0);               // L0 step n
            in0[ub * ISTRIDE + 32 + uj] = h0;              // h0 -> next L0 input
            inB[ub * ISTRIDE + uj]      = h0;              // h0 -> L1 input
            float s = (n + 1 < TSTEPS) ? seq[n + 1] : 0.f;
            in0[ub * ISTRIDE + uj] = fmaxf(fmaf(s, w1j, b1j), 0.f);  // x(n+1)
        }
        if (n > 0) {
            float h1 = upd(gs1, uj, ub, c1);               // L1 step n-1
            inB[ub * ISTRIDE + 32 + uj] = h1;              // h1 -> next L1 input
        }
        __syncthreads();                                   // S2: inputs ready
    }

    // ---- Head: out[b] = [h0_final ; h1_final] . w2 + b2 ----
    // inB[b][0..31] = h0(T-1), inB[b][32..63] = h1(T-1)
    if (tid < 32) {
        const float* hb = inB + tid * ISTRIDE;
        float acc = 0.f;
#pragma unroll
        for (int k = 0; k < 64; k++) acc = fmaf(w2s[k], hb[k], acc);
        out[blockIdx.x * 32 + tid] = acc + b2[0];
    }
}

extern "C" void kernel_launch(void* const* d_in, const int* in_sizes, int n_in,
                              void* d_out, int out_size) {
    const float* tensor = (const float*)d_in[0];
    const float* w1     = (const float*)d_in[1];
    const float* b1     = (const float*)d_in[2];
    const float* Wih0   = (const float*)d_in[3];
    const float* Whh0   = (const float*)d_in[4];
    const float* bih0   = (const float*)d_in[5];
    const float* bhh0   = (const float*)d_in[6];
    const float* Wih1   = (const float*)d_in[7];
    const float* Whh1   = (const float*)d_in[8];
    const float* bih1   = (const float*)d_in[9];
    const float* bhh1   = (const float*)d_in[10];
    const float* w2     = (const float*)d_in[11];
    const float* b2     = (const float*)d_in[12];
    float* out = (float*)d_out;

    int Btot = in_sizes[0] / TSTEPS;   // 4096
    int grid = (Btot + 31) / 32;       // 128 CTAs

    cudaFuncSetAttribute(lstm_fused_kernel,
                         cudaFuncAttributeMaxDynamicSharedMemorySize, SMEM_BYTES);
    lstm_fused_kernel<<<grid, NTHREADS, SMEM_BYTES>>>(
        tensor, w1, b1, Wih0, Whh0, bih0, bhh0,
        Wih1, Whh1, bih1, bhh1, w2, b2, out);
}

// round 10
// speedup vs baseline: 1.7197x; 1.7197x over previous
#include <cuda_runtime.h>

#define TSTEPS   512
#define NTHREADS 512

// SMEM geometry (floats)
#define WST  76          // weight row stride: k' 0..31 at kh*36, pad to 76
#define IST  72          // input row per batch: kh*36 + k' (x|h), pad to 72
#define GSB  132         // gs per-batch stride: 128 gates + 4
#define GSK  4240        // gs kh-plane stride: 32*132 + 16
#define GSL  (2*GSK)     // gs per-layer: 8480

#define OFF_W    0           // 2 * 128*76 = 19456
#define WLAY     (128*WST)   // 9728
#define OFF_GS   19456       // 2 * 8480 = 16960
#define OFF_IN0  36416       // 32*72
#define OFF_IN1  38720       // 32*72
#define OFF_B0   41024       // 128
#define OFF_B1   41152       // 128
#define OFF_W1S  41280       // 32
#define OFF_B1S  41312       // 32
#define OFF_W2S  41344       // 64
#define SMEM_FLOATS 41408
#define SMEM_BYTES  (SMEM_FLOATS * 4)   // 165632

typedef unsigned long long ull;

__device__ __forceinline__ float sum2(ull v) {
    float lo, hi;
    asm("mov.b64 {%0,%1}, %2;" : "=f"(lo), "=f"(hi) : "l"(v));
    return lo + hi;
}
__device__ __forceinline__ void ffma2(ull& d, ull a, ull b) {
    asm("fma.rn.f32x2 %0, %1, %2, %0;" : "+l"(d) : "l"(a), "l"(b));
}
__device__ __forceinline__ float sigm(float v) {
    float e = __expf(-v);
    return __fdividef(1.0f, 1.0f + e);
}
__device__ __forceinline__ float tanh_(float v) {
    float e = __expf(-2.0f * v);
    return __fdividef(2.0f, 1.0f + e) - 1.0f;
}

// Gate partial-GEMM: thread computes 8 rows (rg*8..+7) x 4 batches (bq+8i)
// over one 32-k half. Wb includes layer+kh offset; inb includes kh offset;
// gsb includes layer+kh offset. Bytes/MAC = 1.5.
__device__ __forceinline__ void gate_phase(const float* __restrict__ Wb,
                                           const float* __restrict__ inb,
                                           float* __restrict__ gsb,
                                           int rg, int bq) {
    ull acc[8][4];
#pragma unroll
    for (int j = 0; j < 8; j++)
#pragma unroll
        for (int i = 0; i < 4; i++) acc[j][i] = 0ull;

    const float* wr = Wb + rg * 8 * WST;
#pragma unroll
    for (int kq = 0; kq < 8; kq++) {
        ulonglong2 in[4];
#pragma unroll
        for (int i = 0; i < 4; i++)
            in[i] = *(const ulonglong2*)(inb + (bq + 8 * i) * IST + kq * 4);
#pragma unroll
        for (int j = 0; j < 8; j++) {
            ulonglong2 w = *(const ulonglong2*)(wr + j * WST + kq * 4);
#pragma unroll
            for (int i = 0; i < 4; i++) {
                ffma2(acc[j][i], w.x, in[i].x);
                ffma2(acc[j][i], w.y, in[i].y);
            }
        }
    }
#pragma unroll
    for (int i = 0; i < 4; i++) {
        float4 v0, v1;
        v0.x = sum2(acc[0][i]); v0.y = sum2(acc[1][i]);
        v0.z = sum2(acc[2][i]); v0.w = sum2(acc[3][i]);
        v1.x = sum2(acc[4][i]); v1.y = sum2(acc[5][i]);
        v1.z = sum2(acc[6][i]); v1.w = sum2(acc[7][i]);
        float* p = gsb + (bq + 8 * i) * GSB + rg * 8;
        *(float4*)p       = v0;
        *(float4*)(p + 4) = v1;
    }
}

__global__ void __launch_bounds__(NTHREADS, 1)
lstm_fused_kernel(const float* __restrict__ tensor,
                  const float* __restrict__ w1,   const float* __restrict__ b1,
                  const float* __restrict__ Wih0, const float* __restrict__ Whh0,
                  const float* __restrict__ bih0, const float* __restrict__ bhh0,
                  const float* __restrict__ Wih1, const float* __restrict__ Whh1,
                  const float* __restrict__ bih1, const float* __restrict__ bhh1,
                  const float* __restrict__ w2,   const float* __restrict__ b2,
                  float* __restrict__ out) {
    extern __shared__ float smem[];
    float* in0 = smem + OFF_IN0;
    float* in1 = smem + OFF_IN1;

    const int tid = threadIdx.x;
    const int lay = tid >> 8;           // warps 0-7: layer0, 8-15: layer1
    const int u   = tid & 255;
    // Gate mapping: kh in bit0, bq in bits1-3 (bank-phase verified), rg high
    const int kh = u & 1;
    const int bq = (u >> 1) & 7;
    const int rg = u >> 4;              // 0..15
    // Update mapping
    const int ub = u >> 3;              // batch 0..31
    const int uq = (u & 7) * 4;         // units uq..uq+3

    // ---- Preload weights into SMEM: W[lay][row][kh*36 + k'] ----
    for (int idx = tid; idx < 4096; idx += NTHREADS) {
        int row = idx >> 5, k = idx & 31;
        smem[OFF_W + row * WST + k]             = Wih0[idx];
        smem[OFF_W + row * WST + 36 + k]        = Whh0[idx];
        smem[OFF_W + WLAY + row * WST + k]      = Wih1[idx];
        smem[OFF_W + WLAY + row * WST + 36 + k] = Whh1[idx];
    }
    if (tid < 128) {
        smem[OFF_B0 + tid] = bih0[tid] + bhh0[tid];
        smem[OFF_B1 + tid] = bih1[tid] + bhh1[tid];
    }
    if (tid < 32) { smem[OFF_W1S + tid] = w1[tid]; smem[OFF_B1S + tid] = b1[tid]; }
    if (tid < 64) { smem[OFF_W2S + tid] = w2[tid]; }
    // zero input staging (h slots + pads)
    for (int idx = tid; idx < 2 * 32 * IST; idx += NTHREADS) in0[idx] = 0.f;
    __syncthreads();

    // per-thread invariant registers
    const float* Wb  = smem + OFF_W + lay * WLAY + kh * 36;
    const float* inb = (lay ? in1 : in0) + kh * 36;
    float* gsb = smem + OFF_GS + lay * GSL + kh * GSK;
    const float* gu0 = smem + OFF_GS + lay * GSL + ub * GSB + uq;        // kh0 partials
    const float* gu1 = gu0 + GSK;                                        // kh1 partials
    const float* biasL = smem + (lay ? OFF_B1 : OFF_B0);
    float4 bzi = *(const float4*)(biasL + 0  + uq);
    float4 bzf = *(const float4*)(biasL + 32 + uq);
    float4 bzg = *(const float4*)(biasL + 64 + uq);
    float4 bzo = *(const float4*)(biasL + 96 + uq);
    float4 w1v = *(const float4*)(smem + OFF_W1S + uq);
    float4 b1v = *(const float4*)(smem + OFF_B1S + uq);
    const float* __restrict__ seq = tensor + (long)(blockIdx.x * 32 + ub) * TSTEPS;

    // x(0) into in0 kh0 slot (h slots already zero)
    if (lay == 0) {
        float s = seq[0];
        float4 x;
        x.x = fmaxf(fmaf(s, w1v.x, b1v.x), 0.f);
        x.y = fmaxf(fmaf(s, w1v.y, b1v.y), 0.f);
        x.z = fmaxf(fmaf(s, w1v.z, b1v.z), 0.f);
        x.w = fmaxf(fmaf(s, w1v.w, b1v.w), 0.f);
        *(float4*)&in0[ub * IST + uq] = x;
    }
    float c0 = 0.f, c1 = 0.f, c2 = 0.f, c3 = 0.f;
    __syncthreads();

    // Skewed pipeline: iteration n = L0 step n (warps 0-7) + L1 step n-1 (warps 8-15)
    for (int n = 0; n <= TSTEPS; n++) {
        if (lay == 0) { if (n < TSTEPS) gate_phase(Wb, inb, gsb, rg, bq); }
        else          { if (n > 0)      gate_phase(Wb, inb, gsb, rg, bq); }
        __syncthreads();                                    // S1: gates ready

        bool active = lay ? (n > 0) : (n < TSTEPS);
        if (active) {
            float4 pi0 = *(const float4*)(gu0 + 0);
            float4 pi1 = *(const float4*)(gu1 + 0);
            float4 pf0 = *(const float4*)(gu0 + 32);
            float4 pf1 = *(const float4*)(gu1 + 32);
            float4 pg0 = *(const float4*)(gu0 + 64);
            float4 pg1 = *(const float4*)(gu1 + 64);
            float4 po0 = *(const float4*)(gu0 + 96);
            float4 po1 = *(const float4*)(gu1 + 96);
            float iv0 = sigm(pi0.x + pi1.x + bzi.x);
            float iv1 = sigm(pi0.y + pi1.y + bzi.y);
            float iv2 = sigm(pi0.z + pi1.z + bzi.z);
            float iv3 = sigm(pi0.w + pi1.w + bzi.w);
            float fv0 = sigm(pf0.x + pf1.x + bzf.x);
            float fv1 = sigm(pf0.y + pf1.y + bzf.y);
            float fv2 = sigm(pf0.z + pf1.z + bzf.z);
            float fv3 = sigm(pf0.w + pf1.w + bzf.w);
            float gv0 = tanh_(pg0.x + pg1.x + bzg.x);
            float gv1 = tanh_(pg0.y + pg1.y + bzg.y);
            float gv2 = tanh_(pg0.z + pg1.z + bzg.z);
            float gv3 = tanh_(pg0.w + pg1.w + bzg.w);
            float ov0 = sigm(po0.x + po1.x + bzo.x);
            float ov1 = sigm(po0.y + po1.y + bzo.y);
            float ov2 = sigm(po0.z + po1.z + bzo.z);
            float ov3 = sigm(po0.w + po1.w + bzo.w);
            c0 = fmaf(fv0, c0, iv0 * gv0);
            c1 = fmaf(fv1, c1, iv1 * gv1);
            c2 = fmaf(fv2, c2, iv2 * gv2);
            c3 = fmaf(fv3, c3, iv3 * gv3);
            float4 h;
            h.x = ov0 * tanh_(c0);
            h.y = ov1 * tanh_(c1);
            h.z = ov2 * tanh_(c2);
            h.w = ov3 * tanh_(c3);
            if (lay == 0) {
                *(float4*)&in0[ub * IST + 36 + uq] = h;     // h0 -> next L0 input
                *(float4*)&in1[ub * IST + uq]      = h;     // h0 -> L1 input
                if (n + 1 < TSTEPS) {
                    float s = seq[n + 1];
                    float4 x;
                    x.x = fmaxf(fmaf(s, w1v.x, b1v.x), 0.f);
                    x.y = fmaxf(fmaf(s, w1v.y, b1v.y), 0.f);
                    x.z = fmaxf(fmaf(s, w1v.z, b1v.z), 0.f);
                    x.w = fmaxf(fmaf(s, w1v.w, b1v.w), 0.f);
                    *(float4*)&in0[ub * IST + uq] = x;      // x(n+1)
                }
            } else {
                *(float4*)&in1[ub * IST + 36 + uq] = h;     // h1 -> next L1 input
            }
        }
        __syncthreads();                                    // S2: inputs ready
    }

    // ---- Head: out[b] = [h0_final ; h1_final] . w2 + b2 ----
    // in1[b][0..31] = h0(T-1), in1[b][36..67] = h1(T-1)
    if (tid < 32) {
        const float* hb  = in1 + tid * IST;
        const float* w2s = smem + OFF_W2S;
        float acc = 0.f;
#pragma unroll
        for (int k = 0; k < 32; k++) acc = fmaf(w2s[k], hb[k], acc);
#pragma unroll
        for (int k = 0; k < 32; k++) acc = fmaf(w2s[32 + k], hb[36 + k], acc);
        out[blockIdx.x * 32 + tid] = acc + b2[0];
    }
}

extern "C" void kernel_launch(void* const* d_in, const int* in_sizes, int n_in,
                              void* d_out, int out_size) {
    const float* tensor = (const float*)d_in[0];
    const float* w1     = (const float*)d_in[1];
    const float* b1     = (const float*)d_in[2];
    const float* Wih0   = (const float*)d_in[3];
    const float* Whh0   = (const float*)d_in[4];
    const float* bih0   = (const float*)d_in[5];
    const float* bhh0   = (const float*)d_in[6];
    const float* Wih1   = (const float*)d_in[7];
    const float* Whh1   = (const float*)d_in[8];
    const float* bih1   = (const float*)d_in[9];
    const float* bhh1   = (const float*)d_in[10];
    const float* w2     = (const float*)d_in[11];
    const float* b2     = (const float*)d_in[12];
    float* out = (float*)d_out;

    int Btot = in_sizes[0] / TSTEPS;   // 4096
    int grid = (Btot + 31) / 32;       // 128 CTAs

    cudaFuncSetAttribute(lstm_fused_kernel,
                         cudaFuncAttributeMaxDynamicSharedMemorySize, SMEM_BYTES);
    lstm_fused_kernel<<<grid, NTHREADS, SMEM_BYTES>>>(
        tensor, w1, b1, Wih0, Whh0, bih0, bhh0,
        Wih1, Whh1, bih1, bhh1, w2, b2, out);
}

// round 11
// speedup vs baseline: 1.7791x; 1.0346x over previous
#include <cuda_runtime.h>

#define TSTEPS   512
#define NTHREADS 512

// SMEM geometry (floats)
#define WST  76          // weight row stride: k' 0..31 at kh*36, pad to 76
#define IST  72          // input row per batch: kh*36 + k' (x|h), pad to 72
#define GSB  132         // gs per-batch stride: 128 gates + 4
#define GSK  4240        // gs kh-plane stride: 32*132 + 16
#define GSL  (2*GSK)     // gs per-layer: 8480

#define OFF_W    0           // 2 * 128*76 = 19456
#define WLAY     (128*WST)   // 9728
#define OFF_GS   19456       // 2 * 8480 = 16960
#define OFF_IN0  36416       // 32*72  L0 input [x | h0]
#define OFF_I1A  38720       // 32*72  L1 input buffer A [h0 | h1]
#define OFF_I1B  41024       // 32*72  L1 input buffer B [h0 | h1]
#define OFF_B0   43328       // 128
#define OFF_B1   43456       // 128
#define OFF_W1S  43584       // 32
#define OFF_B1S  43616       // 32
#define OFF_W2S  43648       // 64
#define SMEM_FLOATS 43712
#define SMEM_BYTES  (SMEM_FLOATS * 4)   // 174848

typedef unsigned long long ull;

#define BARS(id, cnt) asm volatile("bar.sync "   #id ", " #cnt ";" ::: "memory")
#define BARA(id, cnt) asm volatile("bar.arrive " #id ", " #cnt ";" ::: "memory")

__device__ __forceinline__ float sum2(ull v) {
    float lo, hi;
    asm("mov.b64 {%0,%1}, %2;" : "=f"(lo), "=f"(hi) : "l"(v));
    return lo + hi;
}
__device__ __forceinline__ void ffma2(ull& d, ull a, ull b) {
    asm("fma.rn.f32x2 %0, %1, %2, %0;" : "+l"(d) : "l"(a), "l"(b));
}
__device__ __forceinline__ float sigm(float v) {
    float e = __expf(-v);
    return __fdividef(1.0f, 1.0f + e);
}
__device__ __forceinline__ float tanh_(float v) {
    float e = __expf(-2.0f * v);
    return __fdividef(2.0f, 1.0f + e) - 1.0f;
}

// Gate partial-GEMM: thread computes 8 rows (rg*8..+7) x 4 batches (bq+8i)
// over one 32-k half (kh). Bytes/MAC = 1.5. (Verified conflict-free in R10.)
__device__ __forceinline__ void gate_phase(const float* __restrict__ Wb,
                                           const float* __restrict__ inb,
                                           float* __restrict__ gsb,
                                           int rg, int bq) {
    ull acc[8][4];
#pragma unroll
    for (int j = 0; j < 8; j++)
#pragma unroll
        for (int i = 0; i < 4; i++) acc[j][i] = 0ull;

    const float* wr = Wb + rg * 8 * WST;
#pragma unroll
    for (int kq = 0; kq < 8; kq++) {
        ulonglong2 in[4];
#pragma unroll
        for (int i = 0; i < 4; i++)
            in[i] = *(const ulonglong2*)(inb + (bq + 8 * i) * IST + kq * 4);
#pragma unroll
        for (int j = 0; j < 8; j++) {
            ulonglong2 w = *(const ulonglong2*)(wr + j * WST + kq * 4);
#pragma unroll
            for (int i = 0; i < 4; i++) {
                ffma2(acc[j][i], w.x, in[i].x);
                ffma2(acc[j][i], w.y, in[i].y);
            }
        }
    }
#pragma unroll
    for (int i = 0; i < 4; i++) {
        float4 v0, v1;
        v0.x = sum2(acc[0][i]); v0.y = sum2(acc[1][i]);
        v0.z = sum2(acc[2][i]); v0.w = sum2(acc[3][i]);
        v1.x = sum2(acc[4][i]); v1.y = sum2(acc[5][i]);
        v1.z = sum2(acc[6][i]); v1.w = sum2(acc[7][i]);
        float* p = gsb + (bq + 8 * i) * GSB + rg * 8;
        *(float4*)p       = v0;
        *(float4*)(p + 4) = v1;
    }
}

// Gate partials (2 k-halves) -> activations -> c/h update for 4 units.
__device__ __forceinline__ float4 do_update(const float* gu0, const float* gu1,
                                            float4 bzi, float4 bzf, float4 bzg, float4 bzo,
                                            float& c0, float& c1, float& c2, float& c3) {
    float4 pi0 = *(const float4*)(gu0 + 0),  pi1 = *(const float4*)(gu1 + 0);
    float4 pf0 = *(const float4*)(gu0 + 32), pf1 = *(const float4*)(gu1 + 32);
    float4 pg0 = *(const float4*)(gu0 + 64), pg1 = *(const float4*)(gu1 + 64);
    float4 po0 = *(const float4*)(gu0 + 96), po1 = *(const float4*)(gu1 + 96);
    float iv0 = sigm(pi0.x + pi1.x + bzi.x), iv1 = sigm(pi0.y + pi1.y + bzi.y);
    float iv2 = sigm(pi0.z + pi1.z + bzi.z), iv3 = sigm(pi0.w + pi1.w + bzi.w);
    float fv0 = sigm(pf0.x + pf1.x + bzf.x), fv1 = sigm(pf0.y + pf1.y + bzf.y);
    float fv2 = sigm(pf0.z + pf1.z + bzf.z), fv3 = sigm(pf0.w + pf1.w + bzf.w);
    float gv0 = tanh_(pg0.x + pg1.x + bzg.x), gv1 = tanh_(pg0.y + pg1.y + bzg.y);
    float gv2 = tanh_(pg0.z + pg1.z + bzg.z), gv3 = tanh_(pg0.w + pg1.w + bzg.w);
    float ov0 = sigm(po0.x + po1.x + bzo.x), ov1 = sigm(po0.y + po1.y + bzo.y);
    float ov2 = sigm(po0.z + po1.z + bzo.z), ov3 = sigm(po0.w + po1.w + bzo.w);
    c0 = fmaf(fv0, c0, iv0 * gv0);
    c1 = fmaf(fv1, c1, iv1 * gv1);
    c2 = fmaf(fv2, c2, iv2 * gv2);
    c3 = fmaf(fv3, c3, iv3 * gv3);
    float4 h;
    h.x = ov0 * tanh_(c0);
    h.y = ov1 * tanh_(c1);
    h.z = ov2 * tanh_(c2);
    h.w = ov3 * tanh_(c3);
    return h;
}

__global__ void __launch_bounds__(NTHREADS, 1)
lstm_fused_kernel(const float* __restrict__ tensor,
                  const float* __restrict__ w1,   const float* __restrict__ b1,
                  const float* __restrict__ Wih0, const float* __restrict__ Whh0,
                  const float* __restrict__ bih0, const float* __restrict__ bhh0,
                  const float* __restrict__ Wih1, const float* __restrict__ Whh1,
                  const float* __restrict__ bih1, const float* __restrict__ bhh1,
                  const float* __restrict__ w2,   const float* __restrict__ b2,
                  float* __restrict__ out) {
    extern __shared__ float smem[];
    float* in0  = smem + OFF_IN0;
    float* in1a = smem + OFF_I1A;
    float* in1b = smem + OFF_I1B;

    const int tid = threadIdx.x;
    const int lay = tid >> 8;           // warps 0-7: layer0, 8-15: layer1
    const int u   = tid & 255;
    const int kh = u & 1;
    const int bq = (u >> 1) & 7;
    const int rg = u >> 4;
    const int ub = u >> 3;              // update: batch 0..31
    const int uq = (u & 7) * 4;         // update: units uq..uq+3

    // ---- Preload weights into SMEM: W[lay][row][kh*36 + k'] ----
    for (int idx = tid; idx < 4096; idx += NTHREADS) {
        int row = idx >> 5, k = idx & 31;
        smem[OFF_W + row * WST + k]             = Wih0[idx];
        smem[OFF_W + row * WST + 36 + k]        = Whh0[idx];
        smem[OFF_W + WLAY + row * WST + k]      = Wih1[idx];
        smem[OFF_W + WLAY + row * WST + 36 + k] = Whh1[idx];
    }
    if (tid < 128) {
        smem[OFF_B0 + tid] = bih0[tid] + bhh0[tid];
        smem[OFF_B1 + tid] = bih1[tid] + bhh1[tid];
    }
    if (tid < 32) { smem[OFF_W1S + tid] = w1[tid]; smem[OFF_B1S + tid] = b1[tid]; }
    if (tid < 64) { smem[OFF_W2S + tid] = w2[tid]; }
    // zero all input staging (x & h slots of in0, in1a, in1b)
    for (int idx = tid; idx < 3 * 32 * IST; idx += NTHREADS) in0[idx] = 0.f;
    __syncthreads();

    // per-thread invariants
    const float* biasL = smem + (lay ? OFF_B1 : OFF_B0);
    float4 bzi = *(const float4*)(biasL + 0  + uq);
    float4 bzf = *(const float4*)(biasL + 32 + uq);
    float4 bzg = *(const float4*)(biasL + 64 + uq);
    float4 bzo = *(const float4*)(biasL + 96 + uq);
    const float* Wb = smem + OFF_W + lay * WLAY + kh * 36;
    float* gsb = smem + OFF_GS + lay * GSL + kh * GSK;
    const float* gu0 = smem + OFF_GS + lay * GSL + ub * GSB + uq;
    const float* gu1 = gu0 + GSK;

    if (lay == 0) {
        float4 w1v = *(const float4*)(smem + OFF_W1S + uq);
        float4 b1v = *(const float4*)(smem + OFF_B1S + uq);
        const float* __restrict__ seq = tensor + (long)(blockIdx.x * 32 + ub) * TSTEPS;
        const float* inb = in0 + kh * 36;

        // x(0) into in0 (h-half already zero)
        {
            float s = seq[0];
            float4 x;
            x.x = fmaxf(fmaf(s, w1v.x, b1v.x), 0.f);
            x.y = fmaxf(fmaf(s, w1v.y, b1v.y), 0.f);
            x.z = fmaxf(fmaf(s, w1v.z, b1v.z), 0.f);
            x.w = fmaxf(fmaf(s, w1v.w, b1v.w), 0.f);
            *(float4*)&in0[ub * IST + uq] = x;
        }
        float c0 = 0.f, c1 = 0.f, c2 = 0.f, c3 = 0.f;
        BARS(1, 256);                                   // in0 init visible to group

        for (int t = 0; t < TSTEPS; t++) {
            gate_phase(Wb, inb, gsb, rg, bq);           // gs0(t)
            BARS(1, 256);                               // gs0 ready

            float4 h = do_update(gu0, gu1, bzi, bzf, bzg, bzo, c0, c1, c2, c3);
            *(float4*)&in0[ub * IST + 36 + uq] = h;     // h0 -> next L0 input
            float* bx = (t & 1) ? in1b : in1a;
            BARS(4, 512);                               // backpressure (slack-1)
            *(float4*)&bx[ub * IST + uq] = h;           // h0 -> L1 input buffer
            BARA(3, 512);                               // h0(t) published
            if (t + 1 < TSTEPS) {
                float s = seq[t + 1];
                float4 x;
                x.x = fmaxf(fmaf(s, w1v.x, b1v.x), 0.f);
                x.y = fmaxf(fmaf(s, w1v.y, b1v.y), 0.f);
                x.z = fmaxf(fmaf(s, w1v.z, b1v.z), 0.f);
                x.w = fmaxf(fmaf(s, w1v.w, b1v.w), 0.f);
                *(float4*)&in0[ub * IST + uq] = x;      // x(t+1)
            }
            BARS(1, 256);                               // in0 ready, gs0 free
        }
    } else {
        float c0 = 0.f, c1 = 0.f, c2 = 0.f, c3 = 0.f;
        BARA(4, 512);                                   // prime backpressure (1 round)

        for (int t = 0; t < TSTEPS; t++) {
            BARS(3, 512);                               // h0(t) available in buf t&1
            const float* inb = ((t & 1) ? in1b : in1a) + kh * 36;
            gate_phase(Wb, inb, gsb, rg, bq);           // gs1(t)
            BARA(4, 512);                               // done reading buf t&1
            BARS(2, 256);                               // gs1 ready

            float4 h = do_update(gu0, gu1, bzi, bzf, bzg, bzo, c0, c1, c2, c3);
            *(float4*)&in1a[ub * IST + 36 + uq] = h;    // h1 -> both buffers' h-half
            *(float4*)&in1b[ub * IST + 36 + uq] = h;
            BARS(2, 256);                               // h1 ready, gs1 free
        }
    }

    __syncthreads();

    // ---- Head: out[b] = [h0_final ; h1_final] . w2 + b2 ----
    // final t = 511 (odd) -> in1b: x-half = h0(T-1), h-half = h1(T-1)
    if (tid < 32) {
        const float* hb  = in1b + tid * IST;
        const float* w2s = smem + OFF_W2S;
        float acc = 0.f;
#pragma unroll
        for (int k = 0; k < 32; k++) acc = fmaf(w2s[k], hb[k], acc);
#pragma unroll
        for (int k = 0; k < 32; k++) acc = fmaf(w2s[32 + k], hb[36 + k], acc);
        out[blockIdx.x * 32 + tid] = acc + b2[0];
    }
}

extern "C" void kernel_launch(void* const* d_in, const int* in_sizes, int n_in,
                              void* d_out, int out_size) {
    const float* tensor = (const float*)d_in[0];
    const float* w1     = (const float*)d_in[1];
    const float* b1     = (const float*)d_in[2];
    const float* Wih0   = (const float*)d_in[3];
    const float* Whh0   = (const float*)d_in[4];
    const float* bih0   = (const float*)d_in[5];
    const float* bhh0   = (const float*)d_in[6];
    const float* Wih1   = (const float*)d_in[7];
    const float* Whh1   = (const float*)d_in[8];
    const float* bih1   = (const float*)d_in[9];
    const float* bhh1   = (const float*)d_in[10];
    const float* w2     = (const float*)d_in[11];
    const float* b2     = (const float*)d_in[12];
    float* out = (float*)d_out;

    int Btot = in_sizes[0] / TSTEPS;   // 4096
    int grid = (Btot + 31) / 32;       // 128 CTAs

    cudaFuncSetAttribute(lstm_fused_kernel,
                         cudaFuncAttributeMaxDynamicSharedMemorySize, SMEM_BYTES);
    lstm_fused_kernel<<<grid, NTHREADS, SMEM_BYTES>>>(
        tensor, w1, b1, Wih0, Whh0, bih0, bhh0,
        Wih1, Whh1, bih1, bhh1, w2, b2, out);
}